// round 12
// baseline (speedup 1.0000x reference)
#include <cuda_runtime.h>
#include <math.h>

#define EPS_F 1e-4f

__device__ float2 g_blk[576];       // dense per-block partials: L0 [0,512), L1 [512,576)
__device__ float  g_pts[6];         // points-block partials
__device__ unsigned int g_ctr = 0;  // completion counter (reset by reducer)

__device__ __forceinline__ float clipsig(float x) {
    float e = __expf(-x);
    float p = __fdividef(1.0f, 1.0f + e);
    return fminf(fmaxf(p, EPS_F), 1.0f - EPS_F);
}
__device__ __forceinline__ float softplusf(float x) {
    return (x > 0.0f) ? (x + log1pf(expf(-x))) : log1pf(expf(x));
}
__device__ __forceinline__ float4 fmax4(float4 a, float4 b) {
    return make_float4(fmaxf(a.x, b.x), fmaxf(a.y, b.y),
                       fmaxf(a.z, b.z), fmaxf(a.w, b.w));
}

// ---- Dense body: depth-2 pipelined, clamped loads, branchless epilogue ------------
// logits layout (B=2, CH=8, D,H,W), ch = c*2 + a. bz = b*2+a.
// Requires TH*(W/4) == 256. smem ring: 4 planes of (TH+2) x W/4 float4 (chan-maxed).
// Coordinate clamping is EXACT for max-pool (edge window duplicates edge element).
template<int D, int H, int W, int TD, int TH>
__device__ __forceinline__ void fused_body(const float4* __restrict__ lg, float4* s,
                                           float* rl, float* rc,
                                           int bz, int d0, int h0, int slot) {
    constexpr int W4 = W / 4, HR = TH + 2, DR = TD + 2, PE = HR * W4;
    constexpr int DHW4 = D * H * W / 4, HW4 = H * W4;
    int tid = threadIdx.x;
    int b = bz >> 1, a = bz & 1;
    const float4* __restrict__ base = lg + (size_t)(b * 8 + a) * DHW4;

    // Per-thread halo-entry assignment (PE <= 512 -> at most 2 entries), h clamped
    const int e0 = tid, e1 = tid + 256;
    const bool has1 = (e1 < PE);
    const int row0 = e0 / W4, wv0 = e0 % W4;
    const int row1 = (has1 ? e1 : e0) / W4, wv1 = (has1 ? e1 : e0) % W4;
    const int hc0 = min(max(h0 + row0 - 1, 0), H - 1);
    const int hc1 = min(max(h0 + row1 - 1, 0), H - 1);
    const int sp0 = hc0 * W4 + wv0, sp1 = hc1 * W4 + wv1;

    // Load plane p (global d clamped), channel-max merged at load -> M0, M1
    #define LOADP(p, M0, M1) {                                                  \
        int dcl_ = min(max(d0 + (p) - 1, 0), D - 1);                            \
        int pb_ = dcl_ * HW4;                                                   \
        {                                                                       \
            int i_ = pb_ + sp0;                                                 \
            float4 v0 = __ldg(base + i_);                                       \
            float4 v1 = __ldg(base + i_ + 2 * DHW4);                            \
            float4 v2 = __ldg(base + i_ + 4 * DHW4);                            \
            float4 v3 = __ldg(base + i_ + 6 * DHW4);                            \
            (M0) = fmax4(fmax4(v0, v1), fmax4(v2, v3));                         \
        }                                                                       \
        {                                                                       \
            int i_ = pb_ + sp1;                                                 \
            float4 v0 = __ldg(base + i_);                                       \
            float4 v1 = __ldg(base + i_ + 2 * DHW4);                            \
            float4 v2 = __ldg(base + i_ + 4 * DHW4);                            \
            float4 v3 = __ldg(base + i_ + 6 * DHW4);                            \
            (M1) = fmax4(fmax4(v0, v1), fmax4(v2, v3));                         \
        }                                                                       \
    }
    #define STOREP(p, M0, M1) {                                                 \
        float4* dst_ = s + ((p) & 3) * PE;                                      \
        dst_[e0] = (M0);                                                        \
        if (has1) dst_[e1] = (M1);                                              \
    }

    // Compute coords: fixed (hh, wv) column per thread
    const int wv = tid % W4, hh = tid / W4;
    #define YMP(p, ym, ctr) {                                                   \
        const float4* col_ = s + ((p) & 3) * PE + hh * W4 + wv;                 \
        float4 r0 = col_[0], r1 = col_[W4], r2 = col_[2 * W4];                  \
        (ctr) = r1; (ym) = fmax4(r0, fmax4(r1, r2));                            \
    }

    // Prologue: planes 0,1 -> smem; planes 2 (A), 3 (B) in-flight in regs
    float4 A0, A1, B0, B1;
    LOADP(0, A0, A1)
    LOADP(1, B0, B1)
    STOREP(0, A0, A1)
    STOREP(1, B0, B1)
    LOADP(2, A0, A1)
    LOADP(3, B0, B1)
    __syncthreads();

    float4 ymA, ymB, ymC, ctrB, ctrN, tmpc;
    YMP(0, ymA, tmpc)
    YMP(1, ymB, ctrB)

    const float NEG_EDGE = -3.0e38f;
    float lsum = 0.0f, csum = 0.0f;
    #pragma unroll
    for (int dd = 0; dd < TD; dd++) {
        // store plane dd+2 (loaded 2 iterations ago), prefetch plane dd+4
        if ((dd & 1) == 0) {
            STOREP(dd + 2, A0, A1)
            if (dd + 4 < DR) LOADP(dd + 4, A0, A1)
        } else {
            STOREP(dd + 2, B0, B1)
            if (dd + 4 < DR) LOADP(dd + 4, B0, B1)
        }
        __syncthreads();
        YMP(dd + 2, ymC, ctrN)
        float4 q = fmax4(ymA, fmax4(ymB, ymC));
        float L = __shfl_up_sync(0xffffffffu, q.w, 1);
        float R = __shfl_down_sync(0xffffffffu, q.x, 1);
        if (wv == 0) L = NEG_EDGE;
        if (wv == W4 - 1) R = NEG_EDGE;
        float p0 = fmaxf(L,   fmaxf(q.x, q.y));
        float p1 = fmaxf(q.x, fmaxf(q.y, q.z));
        float p2 = fmaxf(q.y, fmaxf(q.z, q.w));
        float p3 = fmaxf(q.z, fmaxf(q.w, R));
        // Branchless epilogue: always compute, mask by (is-local-max && pr>EPS)
        #define DO_ONE(CC, PP) {                                                \
            float e_ = __expf(-(CC));                                           \
            float pp_ = __fdividef(1.0f, 1.0f + e_);                            \
            float pr_ = fminf(fmaxf(pp_, EPS_F), 1.0f - EPS_F);                 \
            float v_ = __logf(1.0f - pr_) * pr_;                                \
            float m_ = ((PP) == (CC) && pr_ > EPS_F) ? 1.0f : 0.0f;             \
            lsum = fmaf(v_, m_, lsum);                                          \
            csum = fmaf(pr_, m_, csum);                                         \
        }
        DO_ONE(ctrB.x, p0) DO_ONE(ctrB.y, p1) DO_ONE(ctrB.z, p2) DO_ONE(ctrB.w, p3)
        #undef DO_ONE
        ymA = ymB; ymB = ymC; ctrB = ctrN;
    }
    #undef LOADP
    #undef STOREP
    #undef YMP

    #pragma unroll
    for (int o = 16; o; o >>= 1) {
        lsum += __shfl_down_sync(0xffffffffu, lsum, o);
        csum += __shfl_down_sync(0xffffffffu, csum, o);
    }
    int wid = tid >> 5, lid = tid & 31;
    if (lid == 0) { rl[wid] = lsum; rc[wid] = csum; }
    __syncthreads();
    if (tid == 0) {
        float Ls = 0.f, Cs = 0.f;
        #pragma unroll
        for (int i = 0; i < 8; i++) { Ls += rl[i]; Cs += rc[i]; }
        g_blk[slot] = make_float2(Ls, Cs);
    }
}

// ---- Points body (256 threads): runs in last block, concurrent with dense ---------
__device__ void points_body(const float* __restrict__ lg0, const float* __restrict__ lg1,
                            const float* __restrict__ gt0, const float* __restrict__ gt1,
                            const int* __restrict__ co0, const int* __restrict__ co1,
                            const float* __restrict__ wcls) {
    int tid = threadIdx.x;
    __shared__ int   present[2][2][4];
    __shared__ int   voxkey[128];
    __shared__ float s_cl[128];
    __shared__ int   s_first[128];
    __shared__ int   s_a[128], s_d[128], s_h[128], s_w[128];
    __shared__ float acc[6];

    if (tid < 6)  acc[tid] = 0.0f;
    if (tid < 16) ((int*)present)[tid] = 0;
    __syncthreads();

    int level = (tid >> 6) & 1;
    int b = (tid >> 5) & 1;
    int k = tid & 31;
    int D = level ? 32 : 64, H = level ? 64 : 128, W = level ? 64 : 128;
    int DHW = D * H * W;
    const float* lg = level ? lg1 : lg0;

    float l0v = 0.f, l1v = 0.f, l2v = 0.f, l3v = 0.f;
    int cls = 0; float vm = 0.f; bool valid = false;

    if (tid < 128) {
        const int* co = level ? co1 : co0;
        const float* gt = level ? gt1 : gt0;
        const int* c = &co[(b * 32 + k) * 4];
        int a0 = c[0];
        valid = (a0 > -1);
        int a = valid ? a0   : 0;
        int d = valid ? c[1] : 0;
        int h = valid ? c[2] : 0;
        int w = valid ? c[3] : 0;
        int sp = (d * H + h) * W + w;
        float gv = gt[(b * 2 + a) * DHW + sp];
        cls = min(max((int)gv - 1, 0), 3);
        vm = valid ? 1.0f : 0.0f;
        int chbase = (b * 8 + a) * DHW;
        l0v = lg[chbase + sp];
        l1v = lg[chbase + 2 * DHW + sp];
        l2v = lg[chbase + 4 * DHW + sp];
        l3v = lg[chbase + 6 * DHW + sp];
        if (valid) present[level][b][cls] = 1;
        voxkey[tid] = valid ? (((a * D + d) * H + h) * W + w) : -1;
        s_cl[tid] = fmaxf(fmaxf(l0v, l1v), fmaxf(l2v, l3v));
        s_a[tid] = a; s_d[tid] = d; s_h[tid] = h; s_w[tid] = w;
    }
    __syncthreads();

    if (tid < 128) {
        float l[4] = {l0v, l1v, l2v, l3v};
        float p[4];
        #pragma unroll
        for (int cc = 0; cc < 4; cc++) p[cc] = clipsig(l[cc]);
        float pt = p[cls], lt = l[cls];
        float wpos = (1.0f - pt) * wcls[cls] * vm;
        float lpos = softplusf(-lt) * wpos;

        float loth = 0.0f, coth = 0.0f;
        #pragma unroll
        for (int cc = 0; cc < 4; cc++) {
            float wo = fmaxf(p[cc] - (pt - 0.05f), 0.0f);
            wo *= (p[cc] > 0.5f) ? 1.0f : 0.0f;
            wo *= (pt   > 0.5f) ? 1.0f : 0.0f;
            wo *= (1.0f - (float)present[level][b][cc]) * vm;
            loth += softplusf(l[cc]) * wo;
            coth += wo;
        }
        bool first = valid;
        int gbase = tid - k, mykey = voxkey[tid];
        for (int kk = 0; kk < k && first; kk++)
            if (voxkey[gbase + kk] == mykey) first = false;
        s_first[tid] = first ? 1 : 0;

        atomicAdd(&acc[0], lpos);
        atomicAdd(&acc[3], wpos);
        atomicAdd(&acc[2], loth);
        atomicAdd(&acc[5], coth);
    }
    __syncthreads();

    // negmask correction: warp-per-point, lane-per-neighbor (27 lanes active)
    int wid = tid >> 5, lid = tid & 31;
    for (int pi = wid; pi < 128; pi += 8) {
        if (!s_first[pi]) continue;
        int plevel = (pi >> 6) & 1;
        int pb = (pi >> 5) & 1;
        int pD = plevel ? 32 : 64, pH = plevel ? 64 : 128, pW = plevel ? 64 : 128;
        int pDHW = pD * pH * pW;
        const float* plg = plevel ? lg1 : lg0;
        int pchb = (pb * 8 + s_a[pi]) * pDHW;
        float nb = -3.0e38f;
        if (lid < 27) {
            int zz = lid / 9 - 1, yy = (lid % 9) / 3 - 1, xx = lid % 3 - 1;
            int dd = s_d[pi] + zz, hh = s_h[pi] + yy, ww = s_w[pi] + xx;
            if ((unsigned)dd < (unsigned)pD && (unsigned)hh < (unsigned)pH &&
                (unsigned)ww < (unsigned)pW) {
                int nsp = (dd * pH + hh) * pW + ww;
                float m0 = fmaxf(plg[pchb + nsp],            plg[pchb + 2 * pDHW + nsp]);
                float m1 = fmaxf(plg[pchb + 4 * pDHW + nsp], plg[pchb + 6 * pDHW + nsp]);
                nb = fmaxf(m0, m1);
            }
        }
        #pragma unroll
        for (int o = 16; o; o >>= 1)
            nb = fmaxf(nb, __shfl_xor_sync(0xffffffffu, nb, o));
        if (lid == 0) {
            float cl = s_cl[pi];
            if (nb == cl) {
                float pr = clipsig(cl);
                if (pr > EPS_F) {
                    atomicAdd(&acc[1], __logf(1.0f - pr) * pr);
                    atomicAdd(&acc[4], -pr);
                }
            }
        }
    }
    __syncthreads();
    if (tid < 6) g_pts[tid] = acc[tid];
}

// ---- Single mega-kernel: 577 blocks, one wave at 4 blocks/SM ------------------------
__global__ void __launch_bounds__(256, 4)
all_k(const float4* __restrict__ lg0v, const float4* __restrict__ lg1v,
      const float* __restrict__ gt0, const float* __restrict__ gt1,
      const int* __restrict__ co0, const int* __restrict__ co1,
      const float* __restrict__ wcls, float* __restrict__ out) {
    extern __shared__ float4 s[];
    __shared__ float rl[8], rc[8];
    __shared__ bool  s_last;
    int bx = blockIdx.x;
    int tid = threadIdx.x;

    if (bx < 512) {
        // L0: D=64 H=128 W=128, TD=8 TH=8 -> per bz: 8 d-tiles x 16 h-tiles = 128
        int bz = bx >> 7, rem = bx & 127;
        int d0 = (rem >> 4) * 8, h0 = (rem & 15) * 8;
        fused_body<64, 128, 128, 8, 8>(lg0v, s, rl, rc, bz, d0, h0, bx);
    } else if (bx < 576) {
        // L1: D=32 H=64 W=64, TD=8 TH=16 -> per bz: 4 d-tiles x 4 h-tiles = 16
        int i = bx - 512;
        int bz = i >> 4, rem = i & 15;
        int d0 = (rem >> 2) * 8, h0 = (rem & 3) * 16;
        fused_body<32, 64, 64, 8, 16>(lg1v, s, rl, rc, bz, d0, h0, bx);
    } else {
        points_body((const float*)lg0v, (const float*)lg1v, gt0, gt1, co0, co1, wcls);
    }

    // ---- completion: last-arriving block reduces everything and writes out ----
    if (tid == 0) {
        __threadfence();
        unsigned old = atomicAdd(&g_ctr, 1u);
        s_last = (old == 576u);
    }
    __syncthreads();
    if (!s_last) return;

    float Ls = 0.0f, Cs = 0.0f;
    for (int i = tid; i < 576; i += 256) {
        Ls += __ldcg(&g_blk[i].x);
        Cs += __ldcg(&g_blk[i].y);
    }
    #pragma unroll
    for (int o = 16; o; o >>= 1) {
        Ls += __shfl_down_sync(0xffffffffu, Ls, o);
        Cs += __shfl_down_sync(0xffffffffu, Cs, o);
    }
    int wid = tid >> 5, lid = tid & 31;
    if (lid == 0) { rl[wid] = Ls; rc[wid] = Cs; }
    __syncthreads();
    if (tid == 0) {
        float Lt = 0.f, Ct = 0.f;
        #pragma unroll
        for (int i = 0; i < 8; i++) { Lt += rl[i]; Ct += rc[i]; }
        out[0] = __ldcg(&g_pts[0]);
        out[1] = __ldcg(&g_pts[1]) - Lt;   // loss_neg
        out[2] = __ldcg(&g_pts[2]);
        out[3] = __ldcg(&g_pts[3]);
        out[4] = __ldcg(&g_pts[4]) + Ct;   // count_neg
        out[5] = __ldcg(&g_pts[5]);
        g_ctr = 0;                          // reset for next graph replay
    }
}

extern "C" void kernel_launch(void* const* d_in, const int* in_sizes, int n_in,
                              void* d_out, int out_size) {
    // setup_inputs() order: logits0, gtprob0, coords0, logits1, gtprob1, coords1, weight_cls
    const float* lg0 = (const float*)d_in[0];
    const float* gt0 = (const float*)d_in[1];
    const int*   co0 = (const int*)d_in[2];
    const float* lg1 = (const float*)d_in[3];
    const float* gt1 = (const float*)d_in[4];
    const int*   co1 = (const int*)d_in[5];
    const float* wc  = (const float*)d_in[6];
    float* out = (float*)d_out;

    // dynamic smem: 4-plane ring, max(L0: 4*320*16, L1: 4*288*16) = 20480 B
    all_k<<<577, 256, 20480>>>((const float4*)lg0, (const float4*)lg1,
                               gt0, gt1, co0, co1, wc, out);
}

// round 13
// speedup vs baseline: 1.2039x; 1.2039x over previous
#include <cuda_runtime.h>
#include <math.h>

#define EPS_F 1e-4f
#define NEG_BIG (-3.0e38f)

__device__ float2 g_blk[576];       // dense per-block partials: L0 [0,512), L1 [512,576)
__device__ float  g_pts[6];         // points-block partials
__device__ unsigned int g_ctr = 0;  // completion counter (reset by reducer)

__device__ __forceinline__ float clipsig(float x) {
    float e = __expf(-x);
    float p = __fdividef(1.0f, 1.0f + e);
    return fminf(fmaxf(p, EPS_F), 1.0f - EPS_F);
}
__device__ __forceinline__ float softplusf(float x) {
    return (x > 0.0f) ? (x + log1pf(expf(-x))) : log1pf(expf(x));
}
__device__ __forceinline__ float4 fmax4(float4 a, float4 b) {
    return make_float4(fmaxf(a.x, b.x), fmaxf(a.y, b.y),
                       fmaxf(a.z, b.z), fmaxf(a.w, b.w));
}

// ---- Dense body: depth-2 pipeline, 2 planes per barrier, 6-slot smem ring ---------
// logits layout (B=2, CH=8, D,H,W), ch = c*2 + a. bz = b*2+a.
// Requires TH*(W/4) == 256. smem ring: 6 planes of (TH+2) x W/4 float4 (chan-maxed).
template<int D, int H, int W, int TD, int TH>
__device__ __forceinline__ void fused_body(const float4* __restrict__ lg, float4* s,
                                           float* rl, float* rc,
                                           int bz, int d0, int h0, int slot) {
    constexpr int W4 = W / 4, HR = TH + 2, DR = TD + 2, PE = HR * W4;
    constexpr int DHW4 = D * H * W / 4, HW4 = H * W4;
    const float4 nb4 = make_float4(NEG_BIG, NEG_BIG, NEG_BIG, NEG_BIG);
    int tid = threadIdx.x;
    int b = bz >> 1, a = bz & 1;
    const float4* __restrict__ base = lg + (size_t)(b * 8 + a) * DHW4;

    // Per-thread halo-entry assignment (PE <= 512 -> at most 2 entries)
    const int e0 = tid, e1 = tid + 256;
    const bool has1 = (e1 < PE);
    const int row0 = e0 / W4, wv0 = e0 % W4;
    const int row1 = e1 / W4, wv1 = e1 % W4;
    const int h_0 = h0 + row0 - 1, h_1 = h0 + row1 - 1;
    const bool hok0 = (unsigned)h_0 < (unsigned)H;
    const bool hok1 = has1 && ((unsigned)h_1 < (unsigned)H);
    const int sp0 = h_0 * W4 + wv0, sp1 = h_1 * W4 + wv1;

    // Load plane p (global d = d0+p-1), channel-max merged at load -> M0, M1
    #define LOADP(p, M0, M1) {                                                  \
        int d_ = d0 + (p) - 1;                                                  \
        bool dok_ = (unsigned)d_ < (unsigned)D;                                 \
        (M0) = nb4; (M1) = nb4;                                                 \
        if (dok_ && hok0) {                                                     \
            int i_ = d_ * HW4 + sp0;                                            \
            float4 v0 = __ldg(base + i_);                                       \
            float4 v1 = __ldg(base + i_ + 2 * DHW4);                            \
            float4 v2 = __ldg(base + i_ + 4 * DHW4);                            \
            float4 v3 = __ldg(base + i_ + 6 * DHW4);                            \
            (M0) = fmax4(fmax4(v0, v1), fmax4(v2, v3));                         \
        }                                                                       \
        if (dok_ && hok1) {                                                     \
            int i_ = d_ * HW4 + sp1;                                            \
            float4 v0 = __ldg(base + i_);                                       \
            float4 v1 = __ldg(base + i_ + 2 * DHW4);                            \
            float4 v2 = __ldg(base + i_ + 4 * DHW4);                            \
            float4 v3 = __ldg(base + i_ + 6 * DHW4);                            \
            (M1) = fmax4(fmax4(v0, v1), fmax4(v2, v3));                         \
        }                                                                       \
    }
    #define STOREP(p, M0, M1) {                                                 \
        float4* dst_ = s + ((p) % 6) * PE;                                      \
        dst_[e0] = (M0);                                                        \
        if (has1) dst_[e1] = (M1);                                              \
    }

    // Compute coords: fixed (hh, wv) column per thread
    const int wv = tid % W4, hh = tid / W4;
    #define YMP(p, ym, ctr) {                                                   \
        const float4* col_ = s + ((p) % 6) * PE + hh * W4 + wv;                 \
        float4 r0 = col_[0], r1 = col_[W4], r2 = col_[2 * W4];                  \
        (ctr) = r1; (ym) = fmax4(r0, fmax4(r1, r2));                            \
    }
    // Emit one output plane: 3x3x3 window + branchy (work-skipping) epilogue
    #define EMIT() {                                                            \
        float4 q = fmax4(ymA, fmax4(ymB, ymC));                                 \
        float L = __shfl_up_sync(0xffffffffu, q.w, 1);                          \
        float R = __shfl_down_sync(0xffffffffu, q.x, 1);                        \
        if (wv == 0) L = NEG_BIG;                                               \
        if (wv == W4 - 1) R = NEG_BIG;                                          \
        float p0 = fmaxf(L,   fmaxf(q.x, q.y));                                 \
        float p1 = fmaxf(q.x, fmaxf(q.y, q.z));                                 \
        float p2 = fmaxf(q.y, fmaxf(q.z, q.w));                                 \
        float p3 = fmaxf(q.z, fmaxf(q.w, R));                                   \
        DO_ONE(ctrB.x, p0) DO_ONE(ctrB.y, p1)                                   \
        DO_ONE(ctrB.z, p2) DO_ONE(ctrB.w, p3)                                   \
    }
    #define DO_ONE(CC, PP)                                                      \
        if ((PP) == (CC)) {                                                     \
            float pr = clipsig(CC);                                             \
            if (pr > EPS_F) { lsum += __logf(1.0f - pr) * pr; csum += pr; }     \
        }

    // Prologue: planes 0,1 -> smem; planes 2 (A), 3 (B) in-flight in regs
    float4 A0, A1, B0, B1;
    LOADP(0, A0, A1)
    LOADP(1, B0, B1)
    STOREP(0, A0, A1)
    STOREP(1, B0, B1)
    LOADP(2, A0, A1)
    LOADP(3, B0, B1)
    __syncthreads();

    float4 ymA, ymB, ymC, ctrB, ctrN, tmpc;
    YMP(0, ymA, tmpc)
    YMP(1, ymB, ctrB)

    float lsum = 0.0f, csum = 0.0f;
    #pragma unroll
    for (int dd = 0; dd < TD; dd += 2) {
        // store planes dd+2, dd+3 (loaded 1 phase ago); prefetch dd+4, dd+5
        STOREP(dd + 2, A0, A1)
        STOREP(dd + 3, B0, B1)
        if (dd + 4 < DR) LOADP(dd + 4, A0, A1)
        if (dd + 5 < DR) LOADP(dd + 5, B0, B1)
        __syncthreads();
        YMP(dd + 2, ymC, ctrN)
        EMIT()                             // output plane dd
        ymA = ymB; ymB = ymC; ctrB = ctrN;
        YMP(dd + 3, ymC, ctrN)
        EMIT()                             // output plane dd+1
        ymA = ymB; ymB = ymC; ctrB = ctrN;
    }
    #undef DO_ONE
    #undef EMIT
    #undef LOADP
    #undef STOREP
    #undef YMP

    #pragma unroll
    for (int o = 16; o; o >>= 1) {
        lsum += __shfl_down_sync(0xffffffffu, lsum, o);
        csum += __shfl_down_sync(0xffffffffu, csum, o);
    }
    int wid = tid >> 5, lid = tid & 31;
    if (lid == 0) { rl[wid] = lsum; rc[wid] = csum; }
    __syncthreads();
    if (tid == 0) {
        float Ls = 0.f, Cs = 0.f;
        #pragma unroll
        for (int i = 0; i < 8; i++) { Ls += rl[i]; Cs += rc[i]; }
        g_blk[slot] = make_float2(Ls, Cs);
    }
}

// ---- Points body (256 threads): runs in last block, concurrent with dense ---------
__device__ void points_body(const float* __restrict__ lg0, const float* __restrict__ lg1,
                            const float* __restrict__ gt0, const float* __restrict__ gt1,
                            const int* __restrict__ co0, const int* __restrict__ co1,
                            const float* __restrict__ wcls) {
    int tid = threadIdx.x;
    __shared__ int   present[2][2][4];
    __shared__ int   voxkey[128];
    __shared__ float s_cl[128];
    __shared__ int   s_first[128];
    __shared__ int   s_a[128], s_d[128], s_h[128], s_w[128];
    __shared__ float acc[6];

    if (tid < 6)  acc[tid] = 0.0f;
    if (tid < 16) ((int*)present)[tid] = 0;
    __syncthreads();

    int level = (tid >> 6) & 1;
    int b = (tid >> 5) & 1;
    int k = tid & 31;
    int D = level ? 32 : 64, H = level ? 64 : 128, W = level ? 64 : 128;
    int DHW = D * H * W;
    const float* lg = level ? lg1 : lg0;

    float l0v = 0.f, l1v = 0.f, l2v = 0.f, l3v = 0.f;
    int cls = 0; float vm = 0.f; bool valid = false;

    if (tid < 128) {
        const int* co = level ? co1 : co0;
        const float* gt = level ? gt1 : gt0;
        const int* c = &co[(b * 32 + k) * 4];
        int a0 = c[0];
        valid = (a0 > -1);
        int a = valid ? a0   : 0;
        int d = valid ? c[1] : 0;
        int h = valid ? c[2] : 0;
        int w = valid ? c[3] : 0;
        int sp = (d * H + h) * W + w;
        float gv = gt[(b * 2 + a) * DHW + sp];
        cls = min(max((int)gv - 1, 0), 3);
        vm = valid ? 1.0f : 0.0f;
        int chbase = (b * 8 + a) * DHW;
        l0v = lg[chbase + sp];
        l1v = lg[chbase + 2 * DHW + sp];
        l2v = lg[chbase + 4 * DHW + sp];
        l3v = lg[chbase + 6 * DHW + sp];
        if (valid) present[level][b][cls] = 1;
        voxkey[tid] = valid ? (((a * D + d) * H + h) * W + w) : -1;
        s_cl[tid] = fmaxf(fmaxf(l0v, l1v), fmaxf(l2v, l3v));
        s_a[tid] = a; s_d[tid] = d; s_h[tid] = h; s_w[tid] = w;
    }
    __syncthreads();

    if (tid < 128) {
        float l[4] = {l0v, l1v, l2v, l3v};
        float p[4];
        #pragma unroll
        for (int cc = 0; cc < 4; cc++) p[cc] = clipsig(l[cc]);
        float pt = p[cls], lt = l[cls];
        float wpos = (1.0f - pt) * wcls[cls] * vm;
        float lpos = softplusf(-lt) * wpos;

        float loth = 0.0f, coth = 0.0f;
        #pragma unroll
        for (int cc = 0; cc < 4; cc++) {
            float wo = fmaxf(p[cc] - (pt - 0.05f), 0.0f);
            wo *= (p[cc] > 0.5f) ? 1.0f : 0.0f;
            wo *= (pt   > 0.5f) ? 1.0f : 0.0f;
            wo *= (1.0f - (float)present[level][b][cc]) * vm;
            loth += softplusf(l[cc]) * wo;
            coth += wo;
        }
        bool first = valid;
        int gbase = tid - k, mykey = voxkey[tid];
        for (int kk = 0; kk < k && first; kk++)
            if (voxkey[gbase + kk] == mykey) first = false;
        s_first[tid] = first ? 1 : 0;

        atomicAdd(&acc[0], lpos);
        atomicAdd(&acc[3], wpos);
        atomicAdd(&acc[2], loth);
        atomicAdd(&acc[5], coth);
    }
    __syncthreads();

    // negmask correction: warp-per-point, lane-per-neighbor (27 lanes active)
    int wid = tid >> 5, lid = tid & 31;
    for (int pi = wid; pi < 128; pi += 8) {
        if (!s_first[pi]) continue;
        int plevel = (pi >> 6) & 1;
        int pb = (pi >> 5) & 1;
        int pD = plevel ? 32 : 64, pH = plevel ? 64 : 128, pW = plevel ? 64 : 128;
        int pDHW = pD * pH * pW;
        const float* plg = plevel ? lg1 : lg0;
        int pchb = (pb * 8 + s_a[pi]) * pDHW;
        float nb = NEG_BIG;
        if (lid < 27) {
            int zz = lid / 9 - 1, yy = (lid % 9) / 3 - 1, xx = lid % 3 - 1;
            int dd = s_d[pi] + zz, hh = s_h[pi] + yy, ww = s_w[pi] + xx;
            if ((unsigned)dd < (unsigned)pD && (unsigned)hh < (unsigned)pH &&
                (unsigned)ww < (unsigned)pW) {
                int nsp = (dd * pH + hh) * pW + ww;
                float m0 = fmaxf(plg[pchb + nsp],            plg[pchb + 2 * pDHW + nsp]);
                float m1 = fmaxf(plg[pchb + 4 * pDHW + nsp], plg[pchb + 6 * pDHW + nsp]);
                nb = fmaxf(m0, m1);
            }
        }
        #pragma unroll
        for (int o = 16; o; o >>= 1)
            nb = fmaxf(nb, __shfl_xor_sync(0xffffffffu, nb, o));
        if (lid == 0) {
            float cl = s_cl[pi];
            if (nb == cl) {
                float pr = clipsig(cl);
                if (pr > EPS_F) {
                    atomicAdd(&acc[1], __logf(1.0f - pr) * pr);
                    atomicAdd(&acc[4], -pr);
                }
            }
        }
    }
    __syncthreads();
    if (tid < 6) g_pts[tid] = acc[tid];
}

// ---- Single mega-kernel: 577 blocks, one wave at 4 blocks/SM ------------------------
__global__ void __launch_bounds__(256, 4)
all_k(const float4* __restrict__ lg0v, const float4* __restrict__ lg1v,
      const float* __restrict__ gt0, const float* __restrict__ gt1,
      const int* __restrict__ co0, const int* __restrict__ co1,
      const float* __restrict__ wcls, float* __restrict__ out) {
    extern __shared__ float4 s[];
    __shared__ float rl[8], rc[8];
    __shared__ bool  s_last;
    int bx = blockIdx.x;
    int tid = threadIdx.x;

    if (bx < 512) {
        // L0: D=64 H=128 W=128, TD=8 TH=8 -> per bz: 8 d-tiles x 16 h-tiles = 128
        int bz = bx >> 7, rem = bx & 127;
        int d0 = (rem >> 4) * 8, h0 = (rem & 15) * 8;
        fused_body<64, 128, 128, 8, 8>(lg0v, s, rl, rc, bz, d0, h0, bx);
    } else if (bx < 576) {
        // L1: D=32 H=64 W=64, TD=8 TH=16 -> per bz: 4 d-tiles x 4 h-tiles = 16
        int i = bx - 512;
        int bz = i >> 4, rem = i & 15;
        int d0 = (rem >> 2) * 8, h0 = (rem & 3) * 16;
        fused_body<32, 64, 64, 8, 16>(lg1v, s, rl, rc, bz, d0, h0, bx);
    } else {
        points_body((const float*)lg0v, (const float*)lg1v, gt0, gt1, co0, co1, wcls);
    }

    // ---- completion: last-arriving block reduces everything and writes out ----
    if (tid == 0) {
        __threadfence();
        unsigned old = atomicAdd(&g_ctr, 1u);
        s_last = (old == 576u);
    }
    __syncthreads();
    if (!s_last) return;

    float Ls = 0.0f, Cs = 0.0f;
    for (int i = tid; i < 576; i += 256) {
        Ls += __ldcg(&g_blk[i].x);
        Cs += __ldcg(&g_blk[i].y);
    }
    #pragma unroll
    for (int o = 16; o; o >>= 1) {
        Ls += __shfl_down_sync(0xffffffffu, Ls, o);
        Cs += __shfl_down_sync(0xffffffffu, Cs, o);
    }
    int wid = tid >> 5, lid = tid & 31;
    if (lid == 0) { rl[wid] = Ls; rc[wid] = Cs; }
    __syncthreads();
    if (tid == 0) {
        float Lt = 0.f, Ct = 0.f;
        #pragma unroll
        for (int i = 0; i < 8; i++) { Lt += rl[i]; Ct += rc[i]; }
        out[0] = __ldcg(&g_pts[0]);
        out[1] = __ldcg(&g_pts[1]) - Lt;   // loss_neg
        out[2] = __ldcg(&g_pts[2]);
        out[3] = __ldcg(&g_pts[3]);
        out[4] = __ldcg(&g_pts[4]) + Ct;   // count_neg
        out[5] = __ldcg(&g_pts[5]);
        g_ctr = 0;                          // reset for next graph replay
    }
}

extern "C" void kernel_launch(void* const* d_in, const int* in_sizes, int n_in,
                              void* d_out, int out_size) {
    // setup_inputs() order: logits0, gtprob0, coords0, logits1, gtprob1, coords1, weight_cls
    const float* lg0 = (const float*)d_in[0];
    const float* gt0 = (const float*)d_in[1];
    const int*   co0 = (const int*)d_in[2];
    const float* lg1 = (const float*)d_in[3];
    const float* gt1 = (const float*)d_in[4];
    const int*   co1 = (const int*)d_in[5];
    const float* wc  = (const float*)d_in[6];
    float* out = (float*)d_out;

    // dynamic smem: 6-slot ring, max(L0: 6*320*16, L1: 6*288*16) = 30720 B
    all_k<<<577, 256, 30720>>>((const float4*)lg0, (const float4*)lg1,
                               gt0, gt1, co0, co1, wc, out);
}